// round 14
// baseline (speedup 1.0000x reference)
#include <cuda_runtime.h>
#include <cstdint>

#define SEQ    2048
#define BATCH  2
#define HID    2048
#define NPH    16
#define HN     128
#define MTOT   (SEQ*BATCH)     // 4096
#define QKVN   (3*HID)         // 6144
#define NHEADS (BATCH*NPH)     // 32
#define ATT_SCALE (1.0f/11.313708498984761f)
#define RS     (BATCH*QKVN)    // 12288, qkv row stride

// Scratch (device globals; no allocation allowed anywhere)
__device__ float g_qkv[(size_t)MTOT * QKVN];
__device__ float g_vT[(size_t)NHEADS * HN * SEQ];
__device__ float g_ctx[(size_t)MTOT * HID];
__device__ float g_hid[(size_t)MTOT * HID];
__device__ float g_wqkv[(size_t)QKVN * HID];
__device__ float g_wout[(size_t)HID * HID];

__device__ __forceinline__ uint32_t f2tf32(float x) {
    uint32_t r; asm("cvt.rna.tf32.f32 %0, %1;" : "=r"(r) : "f"(x)); return r;
}
__device__ __forceinline__ float f2tf32f(float x) {
    return __uint_as_float(f2tf32(x));
}
__device__ __forceinline__ void mma_tf32(float* d, const uint32_t* a, const uint32_t* b) {
    asm volatile(
        "mma.sync.aligned.m16n8k8.row.col.f32.tf32.tf32.f32 "
        "{%0,%1,%2,%3}, {%4,%5,%6,%7}, {%8,%9}, {%0,%1,%2,%3};"
        : "+f"(d[0]), "+f"(d[1]), "+f"(d[2]), "+f"(d[3])
        : "r"(a[0]), "r"(a[1]), "r"(a[2]), "r"(a[3]), "r"(b[0]), "r"(b[1]));
}
__device__ __forceinline__ void ldsm4(uint32_t& r0, uint32_t& r1, uint32_t& r2, uint32_t& r3,
                                      uint32_t addr) {
    asm volatile("ldmatrix.sync.aligned.m8n8.x4.shared.b16 {%0,%1,%2,%3}, [%4];"
                 : "=r"(r0), "=r"(r1), "=r"(r2), "=r"(r3) : "r"(addr));
}
__device__ __forceinline__ void cp16(uint32_t dst, const void* src) {
    asm volatile("cp.async.cg.shared.global [%0], [%1], 16;" :: "r"(dst), "l"(src));
}

// ---------------------------------------------------------------------------
// NT GEMM (unchanged): used for QKV and output projections.
// ---------------------------------------------------------------------------
#define PITCH 36
#define STAGE_BYTES (128 * PITCH * 4)
#define GEMM_SMEM   (6 * STAGE_BYTES)

template <bool ROUND>
__global__ void __launch_bounds__(256, 2)
gemm_nt(const float* __restrict__ A, int lda, long sAz,
        const float* __restrict__ B, int ldb, long sBz,
        float*       __restrict__ C, int ldc, long sCz,
        int K, float alpha)
{
    extern __shared__ __align__(16) char smem[];
    const uint32_t sb = (uint32_t)__cvta_generic_to_shared(smem);

    const int z = blockIdx.z;
    A += (long)z * sAz; B += (long)z * sBz; C += (long)z * sCz;

    const int m0 = blockIdx.y * 128;
    const int n0 = blockIdx.x * 128;
    const int t    = threadIdx.x;
    const int lane = t & 31;
    const int warp = t >> 5;
    const int wm = (warp >> 2) * 64;
    const int wn = (warp & 3)  * 32;
    const int gid = lane >> 2;
    const int tg  = lane & 3;
    const int sub = lane >> 3;
    const int lr  = lane & 7;

    const int crow = t >> 3;
    const int ccol = (t & 7) * 4;

    float acc[4][4][4];
#pragma unroll
    for (int i = 0; i < 4; i++)
#pragma unroll
        for (int j = 0; j < 4; j++)
#pragma unroll
            for (int r = 0; r < 4; r++) acc[i][j][r] = 0.0f;

    auto issue = [&](int kt) {
        const int st = kt % 3;
        const int k0 = kt * 32;
        const uint32_t ab = sb + st * STAGE_BYTES;
        const uint32_t bb = sb + 3 * STAGE_BYTES + st * STAGE_BYTES;
#pragma unroll
        for (int i = 0; i < 4; i++) {
            const int r = crow + 32 * i;
            cp16(ab + (r * PITCH + ccol) * 4, A + (long)(m0 + r) * lda + k0 + ccol);
            cp16(bb + (r * PITCH + ccol) * 4, B + (long)(n0 + r) * ldb + k0 + ccol);
        }
        asm volatile("cp.async.commit_group;" ::: "memory");
    };

    const uint32_t aRowOff = (uint32_t)(wm + lr + (sub & 1) * 8);
    const uint32_t aColOff = (uint32_t)((sub >> 1) * 4);
    const uint32_t bRowOff = (uint32_t)(wn + (sub >> 1) * 8 + lr);
    const uint32_t bColOff = (uint32_t)((sub & 1) * 4);

    const int KT = K / 32;

    issue(0); issue(1);

    for (int kt = 0; kt < KT; kt++) {
        asm volatile("cp.async.wait_group 1;" ::: "memory");
        __syncthreads();
        if (kt + 2 < KT) issue(kt + 2);
        else asm volatile("cp.async.commit_group;" ::: "memory");

        const int st = kt % 3;
        const uint32_t aSt = sb + st * STAGE_BYTES;
        const uint32_t bSt = sb + 3 * STAGE_BYTES + st * STAGE_BYTES;
#pragma unroll
        for (int s = 0; s < 4; s++) {
            const int ks = s * 8;
            uint32_t a[4][4], b[4][2];
#pragma unroll
            for (int mb = 0; mb < 4; mb++) {
                const uint32_t addr = aSt + ((aRowOff + mb * 16) * PITCH + ks + aColOff) * 4;
                ldsm4(a[mb][0], a[mb][1], a[mb][2], a[mb][3], addr);
            }
#pragma unroll
            for (int np = 0; np < 2; np++) {
                const uint32_t addr = bSt + ((bRowOff + np * 16) * PITCH + ks + bColOff) * 4;
                ldsm4(b[np * 2][0], b[np * 2][1], b[np * 2 + 1][0], b[np * 2 + 1][1], addr);
            }
#pragma unroll
            for (int mi = 0; mi < 4; mi++)
#pragma unroll
                for (int ni = 0; ni < 4; ni++)
                    mma_tf32(acc[mi][ni], a[mi], b[ni]);
        }
    }

#pragma unroll
    for (int mi = 0; mi < 4; mi++) {
#pragma unroll
        for (int ni = 0; ni < 4; ni++) {
            const int row = m0 + wm + mi * 16 + gid;
            const int col = n0 + wn + ni * 8 + tg * 2;
            float v0 = acc[mi][ni][0] * alpha, v1 = acc[mi][ni][1] * alpha;
            float v2 = acc[mi][ni][2] * alpha, v3 = acc[mi][ni][3] * alpha;
            if (ROUND) { v0 = f2tf32f(v0); v1 = f2tf32f(v1); v2 = f2tf32f(v2); v3 = f2tf32f(v3); }
            *(float2*)(C + (long)row * ldc + col)       = make_float2(v0, v1);
            *(float2*)(C + (long)(row + 8) * ldc + col) = make_float2(v2, v3);
        }
    }
}

// ---------------------------------------------------------------------------
// Fused flash attention, software-pipelined:
//   per iter: issue(it+2) | wait(it+1) | S(it+1) MMAs queued BEFORE softmax(it)
//   so the tensor pipe stays busy through the scalar softmax chain; then PV(it).
// 3-stage K/V rings; P overlays the dead K slot it%3.
// CTA: 256 thr / 8 warps; warp owns 16 Q rows x full 128-col O tile; TT=64.
// ---------------------------------------------------------------------------
#define TT        64
#define NIT       (SEQ / TT)            // 32
#define KPITCH    132                   // 528 B, mod 128 = 16 -> ldsm ok
#define VPITCH    68                    // 272 B, mod 128 = 16 -> ldsm ok
#define KSTG      (64 * KPITCH * 4)     // 33792
#define VSTG      (128 * VPITCH * 4)    // 34816
#define SM_V_OFF  (3 * KSTG)            // 101376
#define FLASH_SMEM (SM_V_OFF + 3 * VSTG)   // 205824

__global__ void __launch_bounds__(256, 1)
flash_attn(const float* __restrict__ qkv, const float* __restrict__ vT,
           float* __restrict__ ctx)
{
    extern __shared__ __align__(16) char smem[];
    const uint32_t sb = (uint32_t)__cvta_generic_to_shared(smem);

    const int z  = blockIdx.y;
    const int q0 = blockIdx.x * 128;
    const float* Qp = qkv + z * 384;
    const float* Kp = qkv + z * 384 + HN;
    const float* Vp = vT + (size_t)z * HN * SEQ;

    const int t    = threadIdx.x;
    const int lane = t & 31;
    const int warp = t >> 5;
    const int gid  = lane >> 2;
    const int tg   = lane & 3;
    const int sub  = lane >> 3;
    const int lr   = lane & 7;

    const uint32_t KS = sb;
    const uint32_t VS = sb + SM_V_OFF;
    // P overlays K slot (it%3); warp w: rows (w&3)*16.., cols (w>>2)*64..
    const uint32_t pWarpOff = (uint32_t)(((warp & 3) * 16 * KPITCH + (warp >> 2) * 64) * 4);

    // ---- Q staging (contiguous, pitch KPITCH, 128 rows) -> qf registers ----
    {
        const int r  = t >> 1;            // 0..127
        const int cb = (t & 1) * 64;
#pragma unroll
        for (int j = 0; j < 16; j++)
            cp16(KS + (r * KPITCH + cb + j * 4) * 4,
                 Qp + (long)(q0 + r) * RS + cb + j * 4);
        asm volatile("cp.async.commit_group;" ::: "memory");
        asm volatile("cp.async.wait_group 0;" ::: "memory");
        __syncthreads();
    }
    uint32_t qf[16][4];
    {
        const uint32_t aR = (uint32_t)(warp * 16 + lr + (sub & 1) * 8);
#pragma unroll
        for (int ks = 0; ks < 16; ks++)
            ldsm4(qf[ks][0], qf[ks][1], qf[ks][2], qf[ks][3],
                  KS + (aR * KPITCH + ks * 8 + (sub >> 1) * 4) * 4);
    }
    __syncthreads();

    float oacc[16][4];
#pragma unroll
    for (int i = 0; i < 16; i++)
#pragma unroll
        for (int j = 0; j < 4; j++) oacc[i][j] = 0.0f;
    float m0 = -3.402823e38f, m1 = -3.402823e38f, l0 = 0.0f, l1 = 0.0f;

    auto issue = [&](int it) {
        const int st = it % 3;
        const int t0 = it * TT;
        {   // K tile: 64 rows x 128 cols
            const int r  = t >> 2;
            const int cb = (t & 3) * 32;
#pragma unroll
            for (int j = 0; j < 8; j++)
                cp16(KS + st * KSTG + ((r * KPITCH) + cb + j * 4) * 4,
                     Kp + (long)(t0 + r) * RS + cb + j * 4);
        }
        {   // V^T tile: 128 h-rows x 64 t-cols
            const int h  = t >> 1;
            const int cb = (t & 1) * 32;
#pragma unroll
            for (int j = 0; j < 8; j++)
                cp16(VS + st * VSTG + ((h * VPITCH) + cb + j * 4) * 4,
                     Vp + (long)h * SEQ + t0 + cb + j * 4);
        }
        asm volatile("cp.async.commit_group;" ::: "memory");
    };

    const uint32_t bR = (uint32_t)((sub >> 1) * 8 + lr);
    const uint32_t bC = (uint32_t)((sub & 1) * 4);
    const uint32_t paR = (uint32_t)(lr + (sub & 1) * 8);
    const uint32_t paC = (uint32_t)((sub >> 1) * 4);

    auto s_compute = [&](int slot, float (*sa)[4]) {
        const uint32_t kst = KS + slot * KSTG;
#pragma unroll
        for (int i = 0; i < 8; i++)
#pragma unroll
            for (int j = 0; j < 4; j++) sa[i][j] = 0.0f;
#pragma unroll
        for (int ks = 0; ks < 16; ks++) {
            uint32_t b[8][2];
#pragma unroll
            for (int np = 0; np < 4; np++)
                ldsm4(b[np * 2][0], b[np * 2][1], b[np * 2 + 1][0], b[np * 2 + 1][1],
                      kst + ((np * 16 + bR) * KPITCH + ks * 8 + bC) * 4);
#pragma unroll
            for (int nt = 0; nt < 8; nt++)
                mma_tf32(sa[nt], qf[ks], b[nt]);
        }
    };

    // prologue: tiles 0,1 in flight; S(0) computed
    issue(0); issue(1);
    asm volatile("cp.async.wait_group 1;" ::: "memory");
    __syncthreads();
    float sacc[8][4];
    s_compute(0, sacc);

    for (int it = 0; it < NIT; it++) {
        // keep the group-count invariant: always commit one group per iter
        if (it + 2 < NIT) issue(it + 2);
        else asm volatile("cp.async.commit_group;" ::: "memory");

        const bool hasNext = (it + 1) < NIT;
        float sacc2[8][4];
        if (hasNext) {
            asm volatile("cp.async.wait_group 1;" ::: "memory");
            __syncthreads();
            // S(it+1) MMAs queued ahead of softmax(it): tensor busy during scalar chain
            s_compute((it + 1) % 3, sacc2);
        }

        // ---- online softmax(it) on sacc (rows gid, gid+8) ----
        float r0 = -3.402823e38f, r1 = -3.402823e38f;
#pragma unroll
        for (int nt = 0; nt < 8; nt++) {
            sacc[nt][0] *= ATT_SCALE; sacc[nt][1] *= ATT_SCALE;
            sacc[nt][2] *= ATT_SCALE; sacc[nt][3] *= ATT_SCALE;
            r0 = fmaxf(r0, fmaxf(sacc[nt][0], sacc[nt][1]));
            r1 = fmaxf(r1, fmaxf(sacc[nt][2], sacc[nt][3]));
        }
        r0 = fmaxf(r0, __shfl_xor_sync(0xffffffffu, r0, 1));
        r0 = fmaxf(r0, __shfl_xor_sync(0xffffffffu, r0, 2));
        r1 = fmaxf(r1, __shfl_xor_sync(0xffffffffu, r1, 1));
        r1 = fmaxf(r1, __shfl_xor_sync(0xffffffffu, r1, 2));
        const float nm0 = fmaxf(m0, r0), nm1 = fmaxf(m1, r1);
        const float a0 = __expf(m0 - nm0), a1 = __expf(m1 - nm1);
        m0 = nm0; m1 = nm1;
        float s0 = 0.0f, s1 = 0.0f;
#pragma unroll
        for (int nt = 0; nt < 8; nt++) {
            float p0 = __expf(sacc[nt][0] - m0), p1 = __expf(sacc[nt][1] - m0);
            float p2 = __expf(sacc[nt][2] - m1), p3 = __expf(sacc[nt][3] - m1);
            s0 += p0 + p1; s1 += p2 + p3;
            sacc[nt][0] = f2tf32f(p0); sacc[nt][1] = f2tf32f(p1);
            sacc[nt][2] = f2tf32f(p2); sacc[nt][3] = f2tf32f(p3);
        }
        s0 += __shfl_xor_sync(0xffffffffu, s0, 1);
        s0 += __shfl_xor_sync(0xffffffffu, s0, 2);
        s1 += __shfl_xor_sync(0xffffffffu, s1, 1);
        s1 += __shfl_xor_sync(0xffffffffu, s1, 2);
        l0 = l0 * a0 + s0;
        l1 = l1 * a1 + s1;
#pragma unroll
        for (int nt = 0; nt < 16; nt++) {
            oacc[nt][0] *= a0; oacc[nt][1] *= a0;
            oacc[nt][2] *= a1; oacc[nt][3] *= a1;
        }

        // ---- P into dead K slot (it%3), then a-fragments via ldmatrix ----
        const uint32_t Pb = KS + (it % 3) * KSTG + pWarpOff;
        char* Pp = smem + (it % 3) * KSTG + pWarpOff;
        __syncwarp();
#pragma unroll
        for (int nt = 0; nt < 8; nt++) {
            *(float2*)(Pp + ((gid)     * KPITCH + nt * 8 + tg * 2) * 4) =
                make_float2(sacc[nt][0], sacc[nt][1]);
            *(float2*)(Pp + ((gid + 8) * KPITCH + nt * 8 + tg * 2) * 4) =
                make_float2(sacc[nt][2], sacc[nt][3]);
        }
        __syncwarp();

        // ---- O += P V  (V slot it%3) ----
        const uint32_t vst = VS + (it % 3) * VSTG;
#pragma unroll
        for (int ks = 0; ks < 8; ks++) {
            uint32_t pa[4];
            ldsm4(pa[0], pa[1], pa[2], pa[3],
                  Pb + (paR * KPITCH + ks * 8 + paC) * 4);
            uint32_t vb[16][2];
#pragma unroll
            for (int np = 0; np < 8; np++)
                ldsm4(vb[np * 2][0], vb[np * 2][1], vb[np * 2 + 1][0], vb[np * 2 + 1][1],
                      vst + ((np * 16 + bR) * VPITCH + ks * 8 + bC) * 4);
#pragma unroll
            for (int nt = 0; nt < 16; nt++)
                mma_tf32(oacc[nt], pa, vb[nt]);
        }
        __syncthreads();

        if (hasNext) {
#pragma unroll
            for (int i = 0; i < 8; i++)
#pragma unroll
                for (int j = 0; j < 4; j++) sacc[i][j] = sacc2[i][j];
        }
    }

    // ---- epilogue: normalize, round to tf32, write ctx ----
    const float inv0 = 1.0f / l0, inv1 = 1.0f / l1;
    const int srow = q0 + warp * 16 + gid;
#pragma unroll
    for (int nt = 0; nt < 16; nt++) {
        const int col = z * HN + nt * 8 + tg * 2;
        *(float2*)(ctx + (long)srow * (BATCH * HID) + col) =
            make_float2(f2tf32f(oacc[nt][0] * inv0), f2tf32f(oacc[nt][1] * inv0));
        *(float2*)(ctx + (long)(srow + 8) * (BATCH * HID) + col) =
            make_float2(f2tf32f(oacc[nt][2] * inv1), f2tf32f(oacc[nt][3] * inv1));
    }
}

// ---------------------------------------------------------------------------
// Elementwise tf32 rounding (for raw inputs)
// ---------------------------------------------------------------------------
__global__ void __launch_bounds__(256)
cvt_tf32(const float* __restrict__ in, float* __restrict__ out, int n4)
{
    const int i = blockIdx.x * 256 + threadIdx.x;
    if (i < n4) {
        float4 v = ((const float4*)in)[i];
        v.x = f2tf32f(v.x); v.y = f2tf32f(v.y);
        v.z = f2tf32f(v.z); v.w = f2tf32f(v.w);
        ((float4*)out)[i] = v;
    }
}

// ---------------------------------------------------------------------------
// V transpose: vT[z][h][t] = qkv[t*12288 + z*384 + 256 + h]
// ---------------------------------------------------------------------------
__global__ void __launch_bounds__(256)
transpose_v(const float* __restrict__ qkv, float* __restrict__ vT)
{
    __shared__ float tile[32][33];
    const int z  = blockIdx.z;
    const int t0 = blockIdx.x * 32;
    const int h0 = blockIdx.y * 32;
    const int x = threadIdx.x, y = threadIdx.y;
#pragma unroll
    for (int i = y; i < 32; i += 8)
        tile[i][x] = qkv[(long)(t0 + i) * RS + z * 384 + 2 * HN + h0 + x];
    __syncthreads();
#pragma unroll
    for (int i = y; i < 32; i += 8)
        vT[((long)z * HN + h0 + i) * SEQ + t0 + x] = tile[x][i];
}

// ---------------------------------------------------------------------------
extern "C" void kernel_launch(void* const* d_in, const int* in_sizes, int n_in,
                              void* d_out, int out_size)
{
    const float* hidden = (const float*)d_in[0];
    const float* w_qkv  = (const float*)d_in[1];
    const float* w_out  = (const float*)d_in[2];
    float* out = (float*)d_out;

    float *qkv, *vT, *ctx, *hidr, *wqkvr, *woutr;
    cudaGetSymbolAddress((void**)&qkv,   g_qkv);
    cudaGetSymbolAddress((void**)&vT,    g_vT);
    cudaGetSymbolAddress((void**)&ctx,   g_ctx);
    cudaGetSymbolAddress((void**)&hidr,  g_hid);
    cudaGetSymbolAddress((void**)&wqkvr, g_wqkv);
    cudaGetSymbolAddress((void**)&woutr, g_wout);

    cudaFuncSetAttribute(gemm_nt<true>,  cudaFuncAttributeMaxDynamicSharedMemorySize, GEMM_SMEM);
    cudaFuncSetAttribute(gemm_nt<false>, cudaFuncAttributeMaxDynamicSharedMemorySize, GEMM_SMEM);
    cudaFuncSetAttribute(flash_attn,     cudaFuncAttributeMaxDynamicSharedMemorySize, FLASH_SMEM);

    // 0) pre-round raw inputs to tf32 values
    cvt_tf32<<<(MTOT * HID / 4 + 255) / 256, 256>>>(hidden, hidr, MTOT * HID / 4);
    cvt_tf32<<<(QKVN * HID / 4 + 255) / 256, 256>>>(w_qkv, wqkvr, QKVN * HID / 4);
    cvt_tf32<<<(HID * HID / 4 + 255) / 256, 256>>>(w_out, woutr, HID * HID / 4);

    // 1) QKV projection (epilogue rounds -> qkv holds tf32 values)
    gemm_nt<true><<<dim3(QKVN / 128, MTOT / 128, 1), 256, GEMM_SMEM>>>(
        hidr, HID, 0,  wqkvr, HID, 0,  qkv, QKVN, 0,  HID, 1.0f);

    // 2) V transpose for the PV half of flash
    transpose_v<<<dim3(SEQ / 32, HN / 32, NHEADS), dim3(32, 8)>>>(qkv, vT);

    // 3) fused scores -> softmax -> P@V   (ctx holds tf32-rounded values)
    flash_attn<<<dim3(SEQ / 128, NHEADS), 256, FLASH_SMEM>>>(qkv, vT, ctx);

    // 4) output projection (no rounding — final result)
    gemm_nt<false><<<dim3(HID / 128, MTOT / 128, 1), 256, GEMM_SMEM>>>(
        ctx, HID, 0,  woutr, HID, 0,  out, HID, 0,  HID, 1.0f);
}

// round 15
// speedup vs baseline: 1.1012x; 1.1012x over previous
#include <cuda_runtime.h>
#include <cstdint>

#define SEQ    2048
#define BATCH  2
#define HID    2048
#define NPH    16
#define HN     128
#define MTOT   (SEQ*BATCH)     // 4096
#define QKVN   (3*HID)         // 6144
#define NHEADS (BATCH*NPH)     // 32
#define ATT_SCALE (1.0f/11.313708498984761f)
#define RS     (BATCH*QKVN)    // 12288

// Scratch (device globals; no allocation allowed anywhere)
__device__ float g_qkv[(size_t)MTOT * QKVN];
__device__ float g_scores[(size_t)NHEADS * SEQ * SEQ];
__device__ float g_vT[(size_t)NHEADS * HN * SEQ];
__device__ float g_ctx[(size_t)MTOT * HID];
__device__ float g_hid[(size_t)MTOT * HID];
__device__ float g_wqkv[(size_t)QKVN * HID];
__device__ float g_wout[(size_t)HID * HID];
__device__ float g_rowc[(size_t)NHEADS * SEQ];   // per-row  max + ln(sumexp)

__device__ __forceinline__ uint32_t f2tf32(float x) {
    uint32_t r; asm("cvt.rna.tf32.f32 %0, %1;" : "=r"(r) : "f"(x)); return r;
}
__device__ __forceinline__ float f2tf32f(float x) {
    return __uint_as_float(f2tf32(x));
}
__device__ __forceinline__ void mma_tf32(float* d, const uint32_t* a, const uint32_t* b) {
    asm volatile(
        "mma.sync.aligned.m16n8k8.row.col.f32.tf32.tf32.f32 "
        "{%0,%1,%2,%3}, {%4,%5,%6,%7}, {%8,%9}, {%0,%1,%2,%3};"
        : "+f"(d[0]), "+f"(d[1]), "+f"(d[2]), "+f"(d[3])
        : "r"(a[0]), "r"(a[1]), "r"(a[2]), "r"(a[3]), "r"(b[0]), "r"(b[1]));
}
__device__ __forceinline__ void ldsm4(uint32_t& r0, uint32_t& r1, uint32_t& r2, uint32_t& r3,
                                      uint32_t addr) {
    asm volatile("ldmatrix.sync.aligned.m8n8.x4.shared.b16 {%0,%1,%2,%3}, [%4];"
                 : "=r"(r0), "=r"(r1), "=r"(r2), "=r"(r3) : "r"(addr));
}
__device__ __forceinline__ void cp16(uint32_t dst, const void* src) {
    asm volatile("cp.async.cg.shared.global [%0], [%1], 16;" :: "r"(dst), "l"(src));
}

// ---------------------------------------------------------------------------
// NT GEMM: C[m,n] = alpha * sum_k A[m,k] * B[n,k].  BM=BN=128, BK=32,
// 256 thr (8 warps 2x4), warp tile 64x32, 3-stage cp.async ring, pitch 36.
// SMAX: A values are raw scores; after each A-tile lands, rework in smem to
// p = tf32(exp(s - c_row)) using the precomputed log-sum-exp constant c_row.
// ROUND: round outputs to tf32 (they feed another GEMM).
// ---------------------------------------------------------------------------
#define PITCH 36
#define STAGE_BYTES (128 * PITCH * 4)
#define GEMM_SMEM   (6 * STAGE_BYTES)

template <bool ROUND, bool SMAX>
__global__ void __launch_bounds__(256, 2)
gemm_nt(const float* __restrict__ A, int lda, long sAz,
        const float* __restrict__ B, int ldb, long sBz,
        float*       __restrict__ C, int ldc, long sCz,
        int K, float alpha, const float* __restrict__ rowc)
{
    extern __shared__ __align__(16) char smem[];
    const uint32_t sb = (uint32_t)__cvta_generic_to_shared(smem);

    const int z = blockIdx.z;
    A += (long)z * sAz; B += (long)z * sBz; C += (long)z * sCz;

    const int m0 = blockIdx.y * 128;
    const int n0 = blockIdx.x * 128;
    const int t    = threadIdx.x;
    const int lane = t & 31;
    const int warp = t >> 5;
    const int wm = (warp >> 2) * 64;
    const int wn = (warp & 3)  * 32;
    const int gid = lane >> 2;
    const int tg  = lane & 3;
    const int sub = lane >> 3;
    const int lr  = lane & 7;

    const int crow = t >> 3;            // 0..31 (+32*i)
    const int ccol = (t & 7) * 4;       // 0,4,...,28

    float cr[4];
    if (SMAX) {
        const long cbase = (long)z * (gridDim.y * 128) + m0;
#pragma unroll
        for (int i = 0; i < 4; i++) cr[i] = rowc[cbase + crow + 32 * i];
    }

    float acc[4][4][4];
#pragma unroll
    for (int i = 0; i < 4; i++)
#pragma unroll
        for (int j = 0; j < 4; j++)
#pragma unroll
            for (int r = 0; r < 4; r++) acc[i][j][r] = 0.0f;

    auto issue = [&](int kt) {
        const int st = kt % 3;
        const int k0 = kt * 32;
        const uint32_t ab = sb + st * STAGE_BYTES;
        const uint32_t bb = sb + 3 * STAGE_BYTES + st * STAGE_BYTES;
#pragma unroll
        for (int i = 0; i < 4; i++) {
            const int r = crow + 32 * i;
            cp16(ab + (r * PITCH + ccol) * 4, A + (long)(m0 + r) * lda + k0 + ccol);
            cp16(bb + (r * PITCH + ccol) * 4, B + (long)(n0 + r) * ldb + k0 + ccol);
        }
        asm volatile("cp.async.commit_group;" ::: "memory");
    };

    const uint32_t aRowOff = (uint32_t)(wm + lr + (sub & 1) * 8);
    const uint32_t aColOff = (uint32_t)((sub >> 1) * 4);
    const uint32_t bRowOff = (uint32_t)(wn + (sub >> 1) * 8 + lr);
    const uint32_t bColOff = (uint32_t)((sub & 1) * 4);

    const int KT = K / 32;

    issue(0); issue(1);

    for (int kt = 0; kt < KT; kt++) {
        asm volatile("cp.async.wait_group 1;" ::: "memory");
        __syncthreads();
        if (kt + 2 < KT) issue(kt + 2);
        else asm volatile("cp.async.commit_group;" ::: "memory");

        const int st = kt % 3;
        const uint32_t aSt = sb + st * STAGE_BYTES;
        const uint32_t bSt = sb + 3 * STAGE_BYTES + st * STAGE_BYTES;

        if (SMAX) {
            // rework the A elements this thread staged: s -> tf32(exp(s - c))
#pragma unroll
            for (int i = 0; i < 4; i++) {
                char* p = smem + st * STAGE_BYTES + ((crow + 32 * i) * PITCH + ccol) * 4;
                float4 v = *(float4*)p;
                v.x = f2tf32f(__expf(v.x - cr[i]));
                v.y = f2tf32f(__expf(v.y - cr[i]));
                v.z = f2tf32f(__expf(v.z - cr[i]));
                v.w = f2tf32f(__expf(v.w - cr[i]));
                *(float4*)p = v;
            }
            __syncthreads();
        }

#pragma unroll
        for (int s = 0; s < 4; s++) {
            const int ks = s * 8;
            uint32_t a[4][4], b[4][2];
#pragma unroll
            for (int mb = 0; mb < 4; mb++) {
                const uint32_t addr = aSt + ((aRowOff + mb * 16) * PITCH + ks + aColOff) * 4;
                ldsm4(a[mb][0], a[mb][1], a[mb][2], a[mb][3], addr);
            }
#pragma unroll
            for (int np = 0; np < 2; np++) {
                const uint32_t addr = bSt + ((bRowOff + np * 16) * PITCH + ks + bColOff) * 4;
                ldsm4(b[np * 2][0], b[np * 2][1], b[np * 2 + 1][0], b[np * 2 + 1][1], addr);
            }
#pragma unroll
            for (int mi = 0; mi < 4; mi++)
#pragma unroll
                for (int ni = 0; ni < 4; ni++)
                    mma_tf32(acc[mi][ni], a[mi], b[ni]);
        }
    }

#pragma unroll
    for (int mi = 0; mi < 4; mi++) {
#pragma unroll
        for (int ni = 0; ni < 4; ni++) {
            const int row = m0 + wm + mi * 16 + gid;
            const int col = n0 + wn + ni * 8 + tg * 2;
            float v0 = acc[mi][ni][0] * alpha, v1 = acc[mi][ni][1] * alpha;
            float v2 = acc[mi][ni][2] * alpha, v3 = acc[mi][ni][3] * alpha;
            if (ROUND) { v0 = f2tf32f(v0); v1 = f2tf32f(v1); v2 = f2tf32f(v2); v3 = f2tf32f(v3); }
            *(float2*)(C + (long)row * ldc + col)       = make_float2(v0, v1);
            *(float2*)(C + (long)(row + 8) * ldc + col) = make_float2(v2, v3);
        }
    }
}

// ---------------------------------------------------------------------------
// Row stats: c[row] = max(s) + ln(sum(exp(s - max))) over each 2048-col row.
// One warp per row; 64 values per lane held in registers (single DRAM read).
// ---------------------------------------------------------------------------
__global__ void __launch_bounds__(256)
row_stats(const float* __restrict__ S, float* __restrict__ rowc)
{
    const int warp = threadIdx.x >> 5;
    const int lane = threadIdx.x & 31;
    const long row = (long)blockIdx.x * 8 + warp;
    const float4* p = (const float4*)(S + row * SEQ);

    float4 v[16];
    float mx = -3.402823e38f;
#pragma unroll
    for (int j = 0; j < 16; j++) {
        v[j] = p[lane + 32 * j];
        mx = fmaxf(mx, fmaxf(fmaxf(v[j].x, v[j].y), fmaxf(v[j].z, v[j].w)));
    }
#pragma unroll
    for (int o = 16; o > 0; o >>= 1) mx = fmaxf(mx, __shfl_xor_sync(0xffffffffu, mx, o));

    float sum = 0.0f;
#pragma unroll
    for (int j = 0; j < 16; j++) {
        sum += __expf(v[j].x - mx) + __expf(v[j].y - mx)
             + __expf(v[j].z - mx) + __expf(v[j].w - mx);
    }
#pragma unroll
    for (int o = 16; o > 0; o >>= 1) sum += __shfl_xor_sync(0xffffffffu, sum, o);

    if (lane == 0) rowc[row] = mx + __logf(sum);
}

// ---------------------------------------------------------------------------
// Elementwise tf32 rounding (for raw inputs)
// ---------------------------------------------------------------------------
__global__ void __launch_bounds__(256)
cvt_tf32(const float* __restrict__ in, float* __restrict__ out, int n4)
{
    const int i = blockIdx.x * 256 + threadIdx.x;
    if (i < n4) {
        float4 v = ((const float4*)in)[i];
        v.x = f2tf32f(v.x); v.y = f2tf32f(v.y);
        v.z = f2tf32f(v.z); v.w = f2tf32f(v.w);
        ((float4*)out)[i] = v;
    }
}

// ---------------------------------------------------------------------------
// V transpose: vT[z][h][t] = qkv[t*12288 + z*384 + 256 + h]
// ---------------------------------------------------------------------------
__global__ void __launch_bounds__(256)
transpose_v(const float* __restrict__ qkv, float* __restrict__ vT)
{
    __shared__ float tile[32][33];
    const int z  = blockIdx.z;
    const int t0 = blockIdx.x * 32;
    const int h0 = blockIdx.y * 32;
    const int x = threadIdx.x, y = threadIdx.y;
#pragma unroll
    for (int i = y; i < 32; i += 8)
        tile[i][x] = qkv[(long)(t0 + i) * RS + z * 384 + 2 * HN + h0 + x];
    __syncthreads();
#pragma unroll
    for (int i = y; i < 32; i += 8)
        vT[((long)z * HN + h0 + i) * SEQ + t0 + x] = tile[x][i];
}

// ---------------------------------------------------------------------------
extern "C" void kernel_launch(void* const* d_in, const int* in_sizes, int n_in,
                              void* d_out, int out_size)
{
    const float* hidden = (const float*)d_in[0];
    const float* w_qkv  = (const float*)d_in[1];
    const float* w_out  = (const float*)d_in[2];
    float* out = (float*)d_out;

    float *qkv, *scores, *vT, *ctx, *hidr, *wqkvr, *woutr, *rowc;
    cudaGetSymbolAddress((void**)&qkv,    g_qkv);
    cudaGetSymbolAddress((void**)&scores, g_scores);
    cudaGetSymbolAddress((void**)&vT,     g_vT);
    cudaGetSymbolAddress((void**)&ctx,    g_ctx);
    cudaGetSymbolAddress((void**)&hidr,   g_hid);
    cudaGetSymbolAddress((void**)&wqkvr,  g_wqkv);
    cudaGetSymbolAddress((void**)&woutr,  g_wout);
    cudaGetSymbolAddress((void**)&rowc,   g_rowc);

    cudaFuncSetAttribute((const void*)gemm_nt<true,  false>, cudaFuncAttributeMaxDynamicSharedMemorySize, GEMM_SMEM);
    cudaFuncSetAttribute((const void*)gemm_nt<false, false>, cudaFuncAttributeMaxDynamicSharedMemorySize, GEMM_SMEM);
    cudaFuncSetAttribute((const void*)gemm_nt<true,  true>,  cudaFuncAttributeMaxDynamicSharedMemorySize, GEMM_SMEM);

    const long SH = (long)SEQ * SEQ;

    // 0) pre-round raw inputs to tf32 values
    cvt_tf32<<<(MTOT * HID / 4 + 255) / 256, 256>>>(hidden, hidr, MTOT * HID / 4);
    cvt_tf32<<<(QKVN * HID / 4 + 255) / 256, 256>>>(w_qkv, wqkvr, QKVN * HID / 4);
    cvt_tf32<<<(HID * HID / 4 + 255) / 256, 256>>>(w_out, woutr, HID * HID / 4);

    // 1) QKV projection (epilogue rounds -> qkv holds tf32 values)
    gemm_nt<true, false><<<dim3(QKVN / 128, MTOT / 128, 1), 256, GEMM_SMEM>>>(
        hidr, HID, 0,  wqkvr, HID, 0,  qkv, QKVN, 0,  HID, 1.0f, nullptr);

    // 2) V transpose for the PV GEMM
    transpose_v<<<dim3(SEQ / 32, HN / 32, NHEADS), dim3(32, 8)>>>(qkv, vT);

    // 3) scores[z] = SCALE * Q_z K_z^T  (raw fp32, feeds stats + PV)
    gemm_nt<false, false><<<dim3(SEQ / 128, SEQ / 128, NHEADS), 256, GEMM_SMEM>>>(
        qkv,      BATCH * QKVN, 384,
        qkv + HN, BATCH * QKVN, 384,
        scores,   SEQ,          SH,
        HN, ATT_SCALE, nullptr);

    // 4) per-row log-sum-exp constants (replaces the softmax pass)
    row_stats<<<NHEADS * SEQ / 8, 256>>>(scores, rowc);

    // 5) ctx[z] = softmax(scores[z]) @ vT[z]^T  — exp applied in-smem (SMAX)
    gemm_nt<true, true><<<dim3(HN / 128, SEQ / 128, NHEADS), 256, GEMM_SMEM>>>(
        scores, SEQ,         SH,
        vT,     SEQ,         (long)HN * SEQ,
        ctx,    BATCH * HID, HN,
        SEQ, 1.0f, rowc);

    // 6) output projection (no rounding — final result)
    gemm_nt<false, false><<<dim3(HID / 128, MTOT / 128, 1), 256, GEMM_SMEM>>>(
        ctx, HID, 0,  woutr, HID, 0,  out, HID, 0,  HID, 1.0f, nullptr);
}

// round 16
// speedup vs baseline: 1.7659x; 1.6036x over previous
#include <cuda_runtime.h>
#include <cstdint>

#define SEQ    2048
#define BATCH  2
#define HID    2048
#define NPH    16
#define HN     128
#define MTOT   (SEQ*BATCH)     // 4096
#define QKVN   (3*HID)         // 6144
#define NHEADS (BATCH*NPH)     // 32
#define ATT_SCALE (1.0f/11.313708498984761f)
#define RS     (BATCH*QKVN)    // 12288
#define NXBLK  (SEQ/128)       // 16 score col-blocks per row

// Scratch (device globals; no allocation allowed anywhere)
__device__ float g_qkv[(size_t)MTOT * QKVN];
__device__ float g_scores[(size_t)NHEADS * SEQ * SEQ];   // holds exp(s) after scores pass
__device__ float g_vT[(size_t)NHEADS * HN * SEQ];
__device__ float g_ctx[(size_t)MTOT * HID];
__device__ float g_hid[(size_t)MTOT * HID];
__device__ float g_wqkv[(size_t)QKVN * HID];
__device__ float g_wout[(size_t)HID * HID];
__device__ float g_psum[(size_t)NHEADS * SEQ * NXBLK];   // per-block exp row sums
__device__ float g_rowinv[(size_t)NHEADS * SEQ];         // 1 / full row sum

__device__ __forceinline__ uint32_t f2tf32(float x) {
    uint32_t r; asm("cvt.rna.tf32.f32 %0, %1;" : "=r"(r) : "f"(x)); return r;
}
__device__ __forceinline__ float f2tf32f(float x) {
    return __uint_as_float(f2tf32(x));
}
__device__ __forceinline__ void mma_tf32(float* d, const uint32_t* a, const uint32_t* b) {
    asm volatile(
        "mma.sync.aligned.m16n8k8.row.col.f32.tf32.tf32.f32 "
        "{%0,%1,%2,%3}, {%4,%5,%6,%7}, {%8,%9}, {%0,%1,%2,%3};"
        : "+f"(d[0]), "+f"(d[1]), "+f"(d[2]), "+f"(d[3])
        : "r"(a[0]), "r"(a[1]), "r"(a[2]), "r"(a[3]), "r"(b[0]), "r"(b[1]));
}
__device__ __forceinline__ void ldsm4(uint32_t& r0, uint32_t& r1, uint32_t& r2, uint32_t& r3,
                                      uint32_t addr) {
    asm volatile("ldmatrix.sync.aligned.m8n8.x4.shared.b16 {%0,%1,%2,%3}, [%4];"
                 : "=r"(r0), "=r"(r1), "=r"(r2), "=r"(r3) : "r"(addr));
}
__device__ __forceinline__ void cp16(uint32_t dst, const void* src) {
    asm volatile("cp.async.cg.shared.global [%0], [%1], 16;" :: "r"(dst), "l"(src));
}

// ---------------------------------------------------------------------------
// NT GEMM: C[m,n] = alpha * sum_k A[m,k] * B[n,k].  BM=BN=128, BK=32,
// 256 thr (8 warps 2x4), warp tile 64x32, 3-stage cp.async ring, pitch 36.
// MODE 0: plain fp32 out.
// MODE 1: out rounded to tf32 (feeds another GEMM).
// MODE 2: out = tf32(exp(alpha*acc)); per-CTA row sums of exp -> psum.
// MODE 3: out = tf32(acc * rowinv[row])  (row-normalized, feeds out-proj).
// ---------------------------------------------------------------------------
#define PITCH 36
#define STAGE_BYTES (128 * PITCH * 4)
#define GEMM_SMEM   (6 * STAGE_BYTES)

template <int MODE>
__global__ void __launch_bounds__(256, 2)
gemm_nt(const float* __restrict__ A, int lda, long sAz,
        const float* __restrict__ B, int ldb, long sBz,
        float*       __restrict__ C, int ldc, long sCz,
        int K, float alpha,
        float* __restrict__ psum, const float* __restrict__ rowinv)
{
    extern __shared__ __align__(16) char smem[];
    const uint32_t sb = (uint32_t)__cvta_generic_to_shared(smem);

    const int z = blockIdx.z;
    A += (long)z * sAz; B += (long)z * sBz; C += (long)z * sCz;

    const int m0 = blockIdx.y * 128;
    const int n0 = blockIdx.x * 128;
    const int t    = threadIdx.x;
    const int lane = t & 31;
    const int warp = t >> 5;
    const int wm = (warp >> 2) * 64;
    const int wn = (warp & 3)  * 32;
    const int gid = lane >> 2;
    const int tg  = lane & 3;
    const int sub = lane >> 3;
    const int lr  = lane & 7;

    const int crow = t >> 3;            // 0..31 (+32*i)
    const int ccol = (t & 7) * 4;       // 0,4,...,28

    float acc[4][4][4];
#pragma unroll
    for (int i = 0; i < 4; i++)
#pragma unroll
        for (int j = 0; j < 4; j++)
#pragma unroll
            for (int r = 0; r < 4; r++) acc[i][j][r] = 0.0f;

    auto issue = [&](int kt) {
        const int st = kt % 3;
        const int k0 = kt * 32;
        const uint32_t ab = sb + st * STAGE_BYTES;
        const uint32_t bb = sb + 3 * STAGE_BYTES + st * STAGE_BYTES;
#pragma unroll
        for (int i = 0; i < 4; i++) {
            const int r = crow + 32 * i;
            cp16(ab + (r * PITCH + ccol) * 4, A + (long)(m0 + r) * lda + k0 + ccol);
            cp16(bb + (r * PITCH + ccol) * 4, B + (long)(n0 + r) * ldb + k0 + ccol);
        }
        asm volatile("cp.async.commit_group;" ::: "memory");
    };

    const uint32_t aRowOff = (uint32_t)(wm + lr + (sub & 1) * 8);
    const uint32_t aColOff = (uint32_t)((sub >> 1) * 4);
    const uint32_t bRowOff = (uint32_t)(wn + (sub >> 1) * 8 + lr);
    const uint32_t bColOff = (uint32_t)((sub & 1) * 4);

    const int KT = K / 32;

    issue(0); issue(1);

    for (int kt = 0; kt < KT; kt++) {
        asm volatile("cp.async.wait_group 1;" ::: "memory");
        __syncthreads();
        if (kt + 2 < KT) issue(kt + 2);
        else asm volatile("cp.async.commit_group;" ::: "memory");

        const int st = kt % 3;
        const uint32_t aSt = sb + st * STAGE_BYTES;
        const uint32_t bSt = sb + 3 * STAGE_BYTES + st * STAGE_BYTES;
#pragma unroll
        for (int s = 0; s < 4; s++) {
            const int ks = s * 8;
            uint32_t a[4][4], b[4][2];
#pragma unroll
            for (int mb = 0; mb < 4; mb++) {
                const uint32_t addr = aSt + ((aRowOff + mb * 16) * PITCH + ks + aColOff) * 4;
                ldsm4(a[mb][0], a[mb][1], a[mb][2], a[mb][3], addr);
            }
#pragma unroll
            for (int np = 0; np < 2; np++) {
                const uint32_t addr = bSt + ((bRowOff + np * 16) * PITCH + ks + bColOff) * 4;
                ldsm4(b[np * 2][0], b[np * 2][1], b[np * 2 + 1][0], b[np * 2 + 1][1], addr);
            }
#pragma unroll
            for (int mi = 0; mi < 4; mi++)
#pragma unroll
                for (int ni = 0; ni < 4; ni++)
                    mma_tf32(acc[mi][ni], a[mi], b[ni]);
        }
    }

    if (MODE == 2) {
        // exp epilogue + deterministic per-CTA row sums
        float* part = (float*)smem;     // 4 x 128 floats; stages are dead after sync
        __syncthreads();                // all warps done reading smem stages
#pragma unroll
        for (int mi = 0; mi < 4; mi++) {
            const int row = m0 + wm + mi * 16 + gid;
            float e0s = 0.0f, e1s = 0.0f;
#pragma unroll
            for (int ni = 0; ni < 4; ni++) {
                const int col = n0 + wn + ni * 8 + tg * 2;
                float v0 = f2tf32f(__expf(acc[mi][ni][0] * alpha));
                float v1 = f2tf32f(__expf(acc[mi][ni][1] * alpha));
                float v2 = f2tf32f(__expf(acc[mi][ni][2] * alpha));
                float v3 = f2tf32f(__expf(acc[mi][ni][3] * alpha));
                *(float2*)(C + (long)row * ldc + col)       = make_float2(v0, v1);
                *(float2*)(C + (long)(row + 8) * ldc + col) = make_float2(v2, v3);
                e0s += v0 + v1; e1s += v2 + v3;
            }
            e0s += __shfl_xor_sync(0xffffffffu, e0s, 1);
            e0s += __shfl_xor_sync(0xffffffffu, e0s, 2);
            e1s += __shfl_xor_sync(0xffffffffu, e1s, 1);
            e1s += __shfl_xor_sync(0xffffffffu, e1s, 2);
            if (tg == 0) {
                part[(warp & 3) * 128 + wm + mi * 16 + gid]     = e0s;
                part[(warp & 3) * 128 + wm + mi * 16 + gid + 8] = e1s;
            }
        }
        __syncthreads();
        if (t < 128) {
            const float tot = part[t] + part[128 + t] + part[256 + t] + part[384 + t];
            psum[((long)z * SEQ + m0 + t) * NXBLK + blockIdx.x] = tot;
        }
        return;
    }

#pragma unroll
    for (int mi = 0; mi < 4; mi++) {
        const int row = m0 + wm + mi * 16 + gid;
        float i0 = 1.0f, i1 = 1.0f;
        if (MODE == 3) {
            i0 = rowinv[(long)z * SEQ + row];
            i1 = rowinv[(long)z * SEQ + row + 8];
        }
#pragma unroll
        for (int ni = 0; ni < 4; ni++) {
            const int col = n0 + wn + ni * 8 + tg * 2;
            float v0 = acc[mi][ni][0] * alpha, v1 = acc[mi][ni][1] * alpha;
            float v2 = acc[mi][ni][2] * alpha, v3 = acc[mi][ni][3] * alpha;
            if (MODE == 3) { v0 *= i0; v1 *= i0; v2 *= i1; v3 *= i1; }
            if (MODE == 1 || MODE == 3) {
                v0 = f2tf32f(v0); v1 = f2tf32f(v1);
                v2 = f2tf32f(v2); v3 = f2tf32f(v3);
            }
            *(float2*)(C + (long)row * ldc + col)       = make_float2(v0, v1);
            *(float2*)(C + (long)(row + 8) * ldc + col) = make_float2(v2, v3);
        }
    }
}

// ---------------------------------------------------------------------------
// rowinv[row] = 1 / sum_{x=0..15} psum[row][x]
// ---------------------------------------------------------------------------
__global__ void __launch_bounds__(256)
rowinv_reduce(const float* __restrict__ psum, float* __restrict__ rowinv)
{
    const long r = (long)blockIdx.x * 256 + threadIdx.x;
    const float4* p = (const float4*)(psum + r * NXBLK);
    float4 a = p[0], b = p[1], c = p[2], d = p[3];
    const float s = ((a.x + a.y) + (a.z + a.w)) + ((b.x + b.y) + (b.z + b.w))
                  + ((c.x + c.y) + (c.z + c.w)) + ((d.x + d.y) + (d.z + d.w));
    rowinv[r] = 1.0f / s;
}

// ---------------------------------------------------------------------------
// Elementwise tf32 rounding (for raw inputs)
// ---------------------------------------------------------------------------
__global__ void __launch_bounds__(256)
cvt_tf32(const float* __restrict__ in, float* __restrict__ out, int n4)
{
    const int i = blockIdx.x * 256 + threadIdx.x;
    if (i < n4) {
        float4 v = ((const float4*)in)[i];
        v.x = f2tf32f(v.x); v.y = f2tf32f(v.y);
        v.z = f2tf32f(v.z); v.w = f2tf32f(v.w);
        ((float4*)out)[i] = v;
    }
}

// ---------------------------------------------------------------------------
// V transpose: vT[z][h][t] = qkv[t*12288 + z*384 + 256 + h]
// ---------------------------------------------------------------------------
__global__ void __launch_bounds__(256)
transpose_v(const float* __restrict__ qkv, float* __restrict__ vT)
{
    __shared__ float tile[32][33];
    const int z  = blockIdx.z;
    const int t0 = blockIdx.x * 32;
    const int h0 = blockIdx.y * 32;
    const int x = threadIdx.x, y = threadIdx.y;
#pragma unroll
    for (int i = y; i < 32; i += 8)
        tile[i][x] = qkv[(long)(t0 + i) * RS + z * 384 + 2 * HN + h0 + x];
    __syncthreads();
#pragma unroll
    for (int i = y; i < 32; i += 8)
        vT[((long)z * HN + h0 + i) * SEQ + t0 + x] = tile[x][i];
}

// ---------------------------------------------------------------------------
extern "C" void kernel_launch(void* const* d_in, const int* in_sizes, int n_in,
                              void* d_out, int out_size)
{
    const float* hidden = (const float*)d_in[0];
    const float* w_qkv  = (const float*)d_in[1];
    const float* w_out  = (const float*)d_in[2];
    float* out = (float*)d_out;

    float *qkv, *scores, *vT, *ctx, *hidr, *wqkvr, *woutr, *psum, *rowinv;
    cudaGetSymbolAddress((void**)&qkv,    g_qkv);
    cudaGetSymbolAddress((void**)&scores, g_scores);
    cudaGetSymbolAddress((void**)&vT,     g_vT);
    cudaGetSymbolAddress((void**)&ctx,    g_ctx);
    cudaGetSymbolAddress((void**)&hidr,   g_hid);
    cudaGetSymbolAddress((void**)&wqkvr,  g_wqkv);
    cudaGetSymbolAddress((void**)&woutr,  g_wout);
    cudaGetSymbolAddress((void**)&psum,   g_psum);
    cudaGetSymbolAddress((void**)&rowinv, g_rowinv);

    cudaFuncSetAttribute((const void*)gemm_nt<0>, cudaFuncAttributeMaxDynamicSharedMemorySize, GEMM_SMEM);
    cudaFuncSetAttribute((const void*)gemm_nt<1>, cudaFuncAttributeMaxDynamicSharedMemorySize, GEMM_SMEM);
    cudaFuncSetAttribute((const void*)gemm_nt<2>, cudaFuncAttributeMaxDynamicSharedMemorySize, GEMM_SMEM);
    cudaFuncSetAttribute((const void*)gemm_nt<3>, cudaFuncAttributeMaxDynamicSharedMemorySize, GEMM_SMEM);

    const long SH = (long)SEQ * SEQ;

    // 0) pre-round raw inputs to tf32 values
    cvt_tf32<<<(MTOT * HID / 4 + 255) / 256, 256>>>(hidden, hidr, MTOT * HID / 4);
    cvt_tf32<<<(QKVN * HID / 4 + 255) / 256, 256>>>(w_qkv, wqkvr, QKVN * HID / 4);
    cvt_tf32<<<(HID * HID / 4 + 255) / 256, 256>>>(w_out, woutr, HID * HID / 4);

    // 1) QKV projection (rounded -> qkv holds tf32 values)
    gemm_nt<1><<<dim3(QKVN / 128, MTOT / 128, 1), 256, GEMM_SMEM>>>(
        hidr, HID, 0,  wqkvr, HID, 0,  qkv, QKVN, 0,  HID, 1.0f, nullptr, nullptr);

    // 2) V transpose for the PV GEMM
    transpose_v<<<dim3(SEQ / 32, HN / 32, NHEADS), dim3(32, 8)>>>(qkv, vT);

    // 3) scores[z] = exp(SCALE * Q_z K_z^T)  + per-block row sums
    gemm_nt<2><<<dim3(NXBLK, SEQ / 128, NHEADS), 256, GEMM_SMEM>>>(
        qkv,      BATCH * QKVN, 384,
        qkv + HN, BATCH * QKVN, 384,
        scores,   SEQ,          SH,
        HN, ATT_SCALE, psum, nullptr);

    // 4) rowinv = 1 / full row sum  (4 MB read; replaces 512 MB softmax pass)
    rowinv_reduce<<<NHEADS * SEQ / 256, 256>>>(psum, rowinv);

    // 5) ctx[z] = (exp(S) @ vT[z]^T) * rowinv  (normalized in epilogue, rounded)
    gemm_nt<3><<<dim3(HN / 128, SEQ / 128, NHEADS), 256, GEMM_SMEM>>>(
        scores, SEQ,         SH,
        vT,     SEQ,         (long)HN * SEQ,
        ctx,    BATCH * HID, HN,
        SEQ, 1.0f, nullptr, rowinv);

    // 6) output projection (plain fp32 out — final result)
    gemm_nt<0><<<dim3(HID / 128, MTOT / 128, 1), 256, GEMM_SMEM>>>(
        ctx, HID, 0,  woutr, HID, 0,  out, HID, 0,  HID, 1.0f, nullptr, nullptr);
}